// round 12
// baseline (speedup 1.0000x reference)
#include <cuda_runtime.h>
#include <cstdint>

// ---------------------------------------------------------------------------
// MLA QKV projection — R12 (resubmit of R11; R11 died to an infra flake):
// mma.sync TF32, 4-stage cp.async pipeline + register double-buffered
// ldmatrix fragments (hide LDSM->MMA latency).
//   Block 128(tok) x 256(feat), BK=32, 8 warps, warp tile 64x64.
//   Hidden read raw (HW tf32 truncation); weights/activations rna-converted.
//   Merged launches: 1 weight-conv, 1 down-GEMM, 1 rms+kpe+vpad, 1 dual up-GEMM.
// ---------------------------------------------------------------------------

#define TOKENS   8192
#define SEQ      4096
#define NHEAD    32
#define D_Q      192
#define D_NOPE   128
#define R_KV     512
#define OUT_CH   96

// ---------------- scratch (__device__ globals; no allocs allowed) ----------
__device__ float g_w12  [8650752];    // [q_a_w | kv_a_w] tf32 (2112*4096)
__device__ float g_w3   [9437184];    // q_b_w   tf32  (6144*1536)
__device__ float g_w4   [4194304];    // kv_b_w  tf32  (8192*512)
__device__ float g_qa   [12582912];   // f32 down-proj out (8192*1536)
__device__ float g_qat  [12582912];   // tf32 normed qa
__device__ float g_ckv  [4718592];    // f32 down-proj out (8192*576)
__device__ float g_ckvnt[4194304];    // tf32 normed ckv (8192*512)

__device__ __forceinline__ uint32_t f2tf(float f) {
    uint32_t r; asm("cvt.rna.tf32.f32 %0, %1;" : "=r"(r) : "f"(f)); return r;
}

__device__ __forceinline__ void mma8(float c[4], const uint32_t a[4], const uint32_t b[2]) {
    asm volatile(
        "mma.sync.aligned.m16n8k8.row.col.f32.tf32.tf32.f32 "
        "{%0,%1,%2,%3},{%4,%5,%6,%7},{%8,%9},{%0,%1,%2,%3};"
        : "+f"(c[0]), "+f"(c[1]), "+f"(c[2]), "+f"(c[3])
        : "r"(a[0]), "r"(a[1]), "r"(a[2]), "r"(a[3]), "r"(b[0]), "r"(b[1]));
}

#define LDSM4(r, addr) \
    asm volatile("ldmatrix.sync.aligned.m8n8.x4.shared.b16 {%0,%1,%2,%3}, [%4];" \
        : "=r"((r)[0]), "=r"((r)[1]), "=r"((r)[2]), "=r"((r)[3]) : "r"(addr))

__device__ __forceinline__ void cpa16(uint32_t dst, const void* src, int nbytes) {
    asm volatile("cp.async.cg.shared.global [%0], [%1], 16, %2;"
                 :: "r"(dst), "l"(src), "r"(nbytes));
}
#define CPA_COMMIT() asm volatile("cp.async.commit_group;" ::: "memory")
#define CPA_WAIT(n)  asm volatile("cp.async.wait_group %0;" :: "n"(n) : "memory")

// epi modes: 1 = query scatter, 2 = key/value scatter, 3 = down (qa|ckv split)
__device__ __forceinline__ void epi_store(int epi, float* __restrict__ C,
                                          float* __restrict__ C2, int t, int n, float v) {
    if (epi == 3) {
        if (n < 1536) C [(size_t)t * 1536 + n] = v;
        else          C2[(size_t)t * 576 + (n - 1536)] = v;
        return;
    }
    const int b = t >> 12;
    const int s = t & (SEQ - 1);
    if (epi == 1) {
        const int h = n / D_Q;
        const int d = n - h * D_Q;
        int col;
        if (d < D_NOPE) col = d;
        else {
            const int j = d - D_NOPE;
            col = D_NOPE + (j >> 1) + ((j & 1) << 5);
        }
        C[((size_t)((b * OUT_CH + h) * SEQ + s)) * D_Q + col] = v;
    } else {
        const int h  = n >> 8;
        const int d  = n & 255;
        const int ch = (d < 128) ? (NHEAD + h) : (2 * NHEAD + h);
        C[((size_t)((b * OUT_CH + ch) * SEQ + s)) * D_Q + (d & 127)] = v;
    }
}

// ---------------------------------------------------------------------------
// GEMM core: C = A[M,K](tokens) * W[N,K]^T(features)
// BM=128, BN=256, BK=32; 256 threads = 8 warps (2x4), warp tile 64x64.
// smem row stride 36; stage = 13824 floats (55296 B); 4 stages = 221184 B.
// Register double-buffered fragments: LDSM(ks+1) issued before mma(ks).
// ---------------------------------------------------------------------------
__device__ __forceinline__ void
gemm_core(const float* __restrict__ A, const float* __restrict__ W,
          float* __restrict__ C, float* __restrict__ C2,
          int N, int K, int t0, int n0, int epi, float* smem)
{
    const int tid   = threadIdx.x;
    const int lane  = tid & 31;
    const int wrp   = tid >> 5;
    const int warpM = wrp >> 2;
    const int warpN = wrp & 3;

    float acc[4][8][4];
#pragma unroll
    for (int i = 0; i < 4; i++)
#pragma unroll
        for (int j = 0; j < 8; j++)
#pragma unroll
            for (int k = 0; k < 4; k++) acc[i][j][k] = 0.f;

    const int KT = K >> 5;

    auto load_tile = [&](int s, int kt) {
        const int kk = kt * 32;
        float* sA = smem + s * 13824;
        float* sB = sA + 4608;
#pragma unroll
        for (int i = 0; i < 4; i++) {
            const int f = tid + i * 256;
            const int row = f >> 3, cq = (f & 7) << 2;
            const uint32_t dst = (uint32_t)__cvta_generic_to_shared(sA + row * 36 + cq);
            cpa16(dst, A + (size_t)(t0 + row) * K + kk + cq, 16);
        }
#pragma unroll
        for (int i = 0; i < 8; i++) {
            const int f = tid + i * 256;
            const int row = f >> 3, cq = (f & 7) << 2;
            const int gn = n0 + row;
            const uint32_t dst = (uint32_t)__cvta_generic_to_shared(sB + row * 36 + cq);
            const int ok = (gn < N) ? 16 : 0;
            cpa16(dst, W + (size_t)(ok ? gn : 0) * K + kk + cq, ok);
        }
        CPA_COMMIT();
    };

    load_tile(0, 0);
    if (KT > 1) load_tile(1, 1);
    if (KT > 2) load_tile(2, 2);

    // hoisted LDSM base addresses (stage 0, byte offsets)
    const uint32_t sb0 = (uint32_t)__cvta_generic_to_shared(smem);
    const int lm = lane >> 3;
    const int lr = lane & 7;
    const int ar = warpM * 64 + (lm & 1) * 8 + lr;
    const int ak = (lm >> 1) * 4;
    const int br = warpN * 64 + (lm >> 1) * 8 + lr;
    const int bk = (lm & 1) * 4;
    uint32_t aB[4], bB[4];
#pragma unroll
    for (int mi = 0; mi < 4; mi++) aB[mi] = sb0 + ((ar + mi * 16) * 36 + ak) * 4;
#pragma unroll
    for (int p = 0; p < 4; p++)   bB[p]  = sb0 + ((4608 + (br + p * 16) * 36 + bk)) * 4;

    for (int kt = 0; kt < KT; kt++) {
        const int rem = KT - 1 - kt;
        if (rem >= 2) CPA_WAIT(2);
        else if (rem == 1) CPA_WAIT(1);
        else CPA_WAIT(0);
        __syncthreads();

        if (kt + 3 < KT) load_tile((kt + 3) & 3, kt + 3);

        const uint32_t so = (kt & 3) * 55296u;

        uint32_t a[2][4][4], b[2][4][4];
        // prime ks=0
#pragma unroll
        for (int mi = 0; mi < 4; mi++) LDSM4(a[0][mi], aB[mi] + so);
#pragma unroll
        for (int p = 0; p < 4; p++)   LDSM4(b[0][p],  bB[p]  + so);

#pragma unroll
        for (int ks = 0; ks < 4; ks++) {
            const int cur = ks & 1, nxt = cur ^ 1;
            if (ks < 3) {
                const uint32_t o = so + (ks + 1) * 32;
#pragma unroll
                for (int mi = 0; mi < 4; mi++) LDSM4(a[nxt][mi], aB[mi] + o);
#pragma unroll
                for (int p = 0; p < 4; p++)   LDSM4(b[nxt][p],  bB[p]  + o);
            }
#pragma unroll
            for (int mi = 0; mi < 4; mi++)
#pragma unroll
                for (int p = 0; p < 4; p++) {
                    mma8(acc[mi][2 * p],     a[cur][mi], &b[cur][p][0]);
                    mma8(acc[mi][2 * p + 1], a[cur][mi], &b[cur][p][2]);
                }
        }
    }

    // epilogue
#pragma unroll
    for (int mi = 0; mi < 4; mi++) {
        const int row = t0 + warpM * 64 + mi * 16 + (lane >> 2);
#pragma unroll
        for (int ni = 0; ni < 8; ni++) {
            const int col = n0 + warpN * 64 + ni * 8 + ((lane & 3) << 1);
            if (col < N) {   // N even -> col+1 also valid
                epi_store(epi, C, C2, row,     col,     acc[mi][ni][0]);
                epi_store(epi, C, C2, row,     col + 1, acc[mi][ni][1]);
                epi_store(epi, C, C2, row + 8, col,     acc[mi][ni][2]);
                epi_store(epi, C, C2, row + 8, col + 1, acc[mi][ni][3]);
            }
        }
    }
}

// down-projection: [qa | ckv] = hidden(raw f32, HW-truncated) @ w12^T
__global__ void __launch_bounds__(256, 1)
gemm_down(const float* __restrict__ A, const float* __restrict__ W,
          float* __restrict__ C, float* __restrict__ C2)
{
    extern __shared__ float smem[];
    gemm_core(A, W, C, C2, 2112, 4096, blockIdx.y * 128, blockIdx.x * 256, 3, smem);
}

// merged up-projections: blocks [0,24) = query (K=1536), [24,56) = kv (K=512)
__global__ void __launch_bounds__(256, 1)
gemm_up(const float* __restrict__ Aq, const float* __restrict__ Wq,
        const float* __restrict__ Akv, const float* __restrict__ Wkv,
        float* __restrict__ out)
{
    extern __shared__ float smem[];
    const int bx = blockIdx.x;
    const int t0 = blockIdx.y * 128;
    if (bx < 24)
        gemm_core(Aq,  Wq,  out, nullptr, 6144, 1536, t0, bx * 256, 1, smem);
    else
        gemm_core(Akv, Wkv, out, nullptr, 8192, 512,  t0, (bx - 24) * 256, 2, smem);
}

// ---------------------------------------------------------------------------
// merged f32 -> tf32(rna) conversion of all four weight tensors
// ---------------------------------------------------------------------------
#define N4_0 1572864   // q_a_w  /4
#define N4_1 589824    // kv_a_w /4
#define N4_2 2359296   // q_b_w  /4
#define N4_3 1048576   // kv_b_w /4

__device__ __forceinline__ float4 cv4(float4 v) {
    v.x = __uint_as_float(f2tf(v.x));
    v.y = __uint_as_float(f2tf(v.y));
    v.z = __uint_as_float(f2tf(v.z));
    v.w = __uint_as_float(f2tf(v.w));
    return v;
}

__global__ void conv_all(const float4* __restrict__ s0, float4* __restrict__ d0,
                         const float4* __restrict__ s1, float4* __restrict__ d1,
                         const float4* __restrict__ s2, float4* __restrict__ d2,
                         const float4* __restrict__ s3, float4* __restrict__ d3)
{
    int i = blockIdx.x * blockDim.x + threadIdx.x;
    if (i < N4_0) { d0[i] = cv4(s0[i]); return; }
    i -= N4_0;
    if (i < N4_1) { d1[i] = cv4(s1[i]); return; }
    i -= N4_1;
    if (i < N4_2) { d2[i] = cv4(s2[i]); return; }
    i -= N4_2;
    if (i < N4_3) { d3[i] = cv4(s3[i]); }
}

// ---------------------------------------------------------------------------
// merged norms: blocks [0,8192) rms(qa); [8192,16384) rms(ckv)+kpe+vpad
// ---------------------------------------------------------------------------
__device__ __forceinline__ float block_sum_256(float v) {
    __shared__ float red[8];
#pragma unroll
    for (int o = 16; o; o >>= 1) v += __shfl_xor_sync(0xffffffffu, v, o);
    const int w = threadIdx.x >> 5, l = threadIdx.x & 31;
    if (l == 0) red[w] = v;
    __syncthreads();
    float r = 0.f;
    if (w == 0) {
        r = (l < 8) ? red[l] : 0.f;
#pragma unroll
        for (int o = 4; o; o >>= 1) r += __shfl_xor_sync(0xffffffffu, r, o);
    }
    return r;
}

__global__ void rms_all(const float* __restrict__ qa, float* __restrict__ qat,
                        const float* __restrict__ qw,
                        const float* __restrict__ ckv, float* __restrict__ ckvnt,
                        const float* __restrict__ kw, float* __restrict__ out)
{
    __shared__ float s_sc;
    const int bid = blockIdx.x;
    if (bid < TOKENS) {
        const float* row = qa + (size_t)bid * 1536;
        float* dst       = qat + (size_t)bid * 1536;
        float ss = 0.f;
        for (int j = threadIdx.x; j < 1536; j += 256) { const float v = row[j]; ss += v * v; }
        const float tot = block_sum_256(ss);
        if (threadIdx.x == 0) s_sc = rsqrtf(tot / 1536.f + 1e-6f);
        __syncthreads();
        const float sc = s_sc;
        for (int j = threadIdx.x; j < 1536; j += 256)
            dst[j] = __uint_as_float(f2tf(row[j] * sc * qw[j]));
    } else {
        const int t = bid - TOKENS;
        const float* row = ckv + (size_t)t * 576;
        float ss = 0.f;
        for (int j = threadIdx.x; j < R_KV; j += 256) { const float v = row[j]; ss += v * v; }
        const float tot = block_sum_256(ss);
        if (threadIdx.x == 0) s_sc = rsqrtf(tot / (float)R_KV + 1e-6f);
        __syncthreads();
        const float sc = s_sc;
        for (int j = threadIdx.x; j < R_KV; j += 256)
            ckvnt[(size_t)t * R_KV + j] = __uint_as_float(f2tf(row[j] * sc * kw[j]));

        const int b = t >> 12;
        const int s = t & (SEQ - 1);
        // k_pe scatter (raw f32, deepseek-transposed) to all 32 key heads
        {
            const int j  = threadIdx.x & 63;
            const int hg = threadIdx.x >> 6;
            const float v = row[R_KV + j];
            const int col = D_NOPE + (j >> 1) + ((j & 1) << 5);
#pragma unroll
            for (int hh = 0; hh < 8; hh++) {
                const int h = hg * 8 + hh;
                out[((size_t)((b * OUT_CH + NHEAD + h) * SEQ + s)) * D_Q + col] = v;
            }
        }
        // value padding zero: out[b, 64+h, s, 128:192]
#pragma unroll
        for (int i = 0; i < 2; i++) {
            const int idx = threadIdx.x + i * 256;   // 0..511
            const int h = idx >> 4, f = idx & 15;
            float4* p = (float4*)(out + ((size_t)((b * OUT_CH + 2 * NHEAD + h) * SEQ + s)) * D_Q + D_NOPE) + f;
            *p = make_float4(0.f, 0.f, 0.f, 0.f);
        }
    }
}

// ---------------------------------------------------------------------------
extern "C" void kernel_launch(void* const* d_in, const int* in_sizes, int n_in,
                              void* d_out, int out_size)
{
    const float* hidden    = (const float*)d_in[0];
    const float* q_a_w     = (const float*)d_in[1];
    const float* q_b_w     = (const float*)d_in[2];
    const float* kv_a_w    = (const float*)d_in[3];
    const float* kv_b_w    = (const float*)d_in[4];
    const float* q_a_ln_w  = (const float*)d_in[5];
    const float* kv_a_ln_w = (const float*)d_in[6];
    float* out = (float*)d_out;

    float *w12, *w3, *w4, *qa, *qat, *ckv, *ckvnt;
    cudaGetSymbolAddress((void**)&w12,   g_w12);
    cudaGetSymbolAddress((void**)&w3,    g_w3);
    cudaGetSymbolAddress((void**)&w4,    g_w4);
    cudaGetSymbolAddress((void**)&qa,    g_qa);
    cudaGetSymbolAddress((void**)&qat,   g_qat);
    cudaGetSymbolAddress((void**)&ckv,   g_ckv);
    cudaGetSymbolAddress((void**)&ckvnt, g_ckvnt);

    const int SMEM = 4 * 13824 * 4;   // 221184 B
    cudaFuncSetAttribute(gemm_down, cudaFuncAttributeMaxDynamicSharedMemorySize, SMEM);
    cudaFuncSetAttribute(gemm_up,   cudaFuncAttributeMaxDynamicSharedMemorySize, SMEM);

    // 1) rna-convert all weights in one launch (hidden stays raw: HW truncates)
    {
        const int total = N4_0 + N4_1 + N4_2 + N4_3;
        conv_all<<<(total + 255) / 256, 256>>>(
            (const float4*)q_a_w,  (float4*)w12,
            (const float4*)kv_a_w, (float4*)(w12 + 6291456),
            (const float4*)q_b_w,  (float4*)w3,
            (const float4*)kv_b_w, (float4*)w4);
    }

    const dim3 blk(256);

    // 2) merged down-projection: [qa | ckv] = hidden @ [q_a_w | kv_a_w]^T
    gemm_down<<<dim3(9, 64), blk, SMEM>>>(hidden, w12, qa, ckv);

    // 3) merged norms + k_pe scatter + value padding
    rms_all<<<2 * TOKENS, 256>>>(qa, qat, q_a_ln_w, ckv, ckvnt, kv_a_ln_w, out);

    // 4) merged up-projections with fused scatter epilogues
    gemm_up<<<dim3(56, 64), blk, SMEM>>>(qat, w3, ckvnt, w4, out);
}

// round 13
// speedup vs baseline: 1.0013x; 1.0013x over previous
#include <cuda_runtime.h>
#include <cstdint>

// ---------------------------------------------------------------------------
// MLA QKV projection — R13: mma.sync TF32, 4-stage cp.async pipeline +
// register-frugal fine-grained fragment pipelining (fix R12's reg spill:
// 254 regs -> ~205 by double-buffering only 1 b-LDSM and spreading a-prefetch).
//   Block 128(tok) x 256(feat), BK=32, 8 warps, warp tile 64x64.
//   Hidden read raw (HW tf32 truncation); weights/activations rna-converted.
// ---------------------------------------------------------------------------

#define TOKENS   8192
#define SEQ      4096
#define NHEAD    32
#define D_Q      192
#define D_NOPE   128
#define R_KV     512
#define OUT_CH   96

// ---------------- scratch (__device__ globals; no allocs allowed) ----------
__device__ float g_w12  [8650752];    // [q_a_w | kv_a_w] tf32 (2112*4096)
__device__ float g_w3   [9437184];    // q_b_w   tf32  (6144*1536)
__device__ float g_w4   [4194304];    // kv_b_w  tf32  (8192*512)
__device__ float g_qa   [12582912];   // f32 down-proj out (8192*1536)
__device__ float g_qat  [12582912];   // tf32 normed qa
__device__ float g_ckv  [4718592];    // f32 down-proj out (8192*576)
__device__ float g_ckvnt[4194304];    // tf32 normed ckv (8192*512)

__device__ __forceinline__ uint32_t f2tf(float f) {
    uint32_t r; asm("cvt.rna.tf32.f32 %0, %1;" : "=r"(r) : "f"(f)); return r;
}

__device__ __forceinline__ void mma8(float c[4], const uint32_t a[4], const uint32_t b[2]) {
    asm volatile(
        "mma.sync.aligned.m16n8k8.row.col.f32.tf32.tf32.f32 "
        "{%0,%1,%2,%3},{%4,%5,%6,%7},{%8,%9},{%0,%1,%2,%3};"
        : "+f"(c[0]), "+f"(c[1]), "+f"(c[2]), "+f"(c[3])
        : "r"(a[0]), "r"(a[1]), "r"(a[2]), "r"(a[3]), "r"(b[0]), "r"(b[1]));
}

#define LDSM4(r, addr) \
    asm volatile("ldmatrix.sync.aligned.m8n8.x4.shared.b16 {%0,%1,%2,%3}, [%4];" \
        : "=r"((r)[0]), "=r"((r)[1]), "=r"((r)[2]), "=r"((r)[3]) : "r"(addr))

__device__ __forceinline__ void cpa16(uint32_t dst, const void* src, int nbytes) {
    asm volatile("cp.async.cg.shared.global [%0], [%1], 16, %2;"
                 :: "r"(dst), "l"(src), "r"(nbytes));
}
#define CPA_COMMIT() asm volatile("cp.async.commit_group;" ::: "memory")
#define CPA_WAIT(n)  asm volatile("cp.async.wait_group %0;" :: "n"(n) : "memory")

// epi modes: 1 = query scatter, 2 = key/value scatter, 3 = down (qa|ckv split)
__device__ __forceinline__ void epi_store(int epi, float* __restrict__ C,
                                          float* __restrict__ C2, int t, int n, float v) {
    if (epi == 3) {
        if (n < 1536) C [(size_t)t * 1536 + n] = v;
        else          C2[(size_t)t * 576 + (n - 1536)] = v;
        return;
    }
    const int b = t >> 12;
    const int s = t & (SEQ - 1);
    if (epi == 1) {
        const int h = n / D_Q;
        const int d = n - h * D_Q;
        int col;
        if (d < D_NOPE) col = d;
        else {
            const int j = d - D_NOPE;
            col = D_NOPE + (j >> 1) + ((j & 1) << 5);
        }
        C[((size_t)((b * OUT_CH + h) * SEQ + s)) * D_Q + col] = v;
    } else {
        const int h  = n >> 8;
        const int d  = n & 255;
        const int ch = (d < 128) ? (NHEAD + h) : (2 * NHEAD + h);
        C[((size_t)((b * OUT_CH + ch) * SEQ + s)) * D_Q + (d & 127)] = v;
    }
}

// ---------------------------------------------------------------------------
// GEMM core: C = A[M,K](tokens) * W[N,K]^T(features)
// BM=128, BN=256, BK=32; 256 threads = 8 warps (2x4), warp tile 64x64.
// smem row stride 36; stage = 13824 floats (55296 B); 4 stages = 221184 B.
// Fine-grained pipeline: b prefetched 1 p-group (8 MMAs) ahead (8 regs),
// a prefetched one ks ahead, one LDSM4 per p-group (32 regs).
// ---------------------------------------------------------------------------
__device__ __forceinline__ void
gemm_core(const float* __restrict__ A, const float* __restrict__ W,
          float* __restrict__ C, float* __restrict__ C2,
          int N, int K, int t0, int n0, int epi, float* smem)
{
    const int tid   = threadIdx.x;
    const int lane  = tid & 31;
    const int wrp   = tid >> 5;
    const int warpM = wrp >> 2;
    const int warpN = wrp & 3;

    float acc[4][8][4];
#pragma unroll
    for (int i = 0; i < 4; i++)
#pragma unroll
        for (int j = 0; j < 8; j++)
#pragma unroll
            for (int k = 0; k < 4; k++) acc[i][j][k] = 0.f;

    const int KT = K >> 5;

    auto load_tile = [&](int s, int kt) {
        const int kk = kt * 32;
        float* sA = smem + s * 13824;
        float* sB = sA + 4608;
#pragma unroll
        for (int i = 0; i < 4; i++) {
            const int f = tid + i * 256;
            const int row = f >> 3, cq = (f & 7) << 2;
            const uint32_t dst = (uint32_t)__cvta_generic_to_shared(sA + row * 36 + cq);
            cpa16(dst, A + (size_t)(t0 + row) * K + kk + cq, 16);
        }
#pragma unroll
        for (int i = 0; i < 8; i++) {
            const int f = tid + i * 256;
            const int row = f >> 3, cq = (f & 7) << 2;
            const int gn = n0 + row;
            const uint32_t dst = (uint32_t)__cvta_generic_to_shared(sB + row * 36 + cq);
            const int ok = (gn < N) ? 16 : 0;
            cpa16(dst, W + (size_t)(ok ? gn : 0) * K + kk + cq, ok);
        }
        CPA_COMMIT();
    };

    load_tile(0, 0);
    if (KT > 1) load_tile(1, 1);
    if (KT > 2) load_tile(2, 2);

    // hoisted LDSM base addresses (stage 0, byte offsets)
    const uint32_t sb0 = (uint32_t)__cvta_generic_to_shared(smem);
    const int lm = lane >> 3;
    const int lr = lane & 7;
    const int ar = warpM * 64 + (lm & 1) * 8 + lr;
    const int ak = (lm >> 1) * 4;
    const int br = warpN * 64 + (lm >> 1) * 8 + lr;
    const int bk = (lm & 1) * 4;
    uint32_t aB[4], bB[4];
#pragma unroll
    for (int mi = 0; mi < 4; mi++) aB[mi] = sb0 + ((ar + mi * 16) * 36 + ak) * 4;
#pragma unroll
    for (int p = 0; p < 4; p++)   bB[p]  = sb0 + ((4608 + (br + p * 16) * 36 + bk)) * 4;

    for (int kt = 0; kt < KT; kt++) {
        const int rem = KT - 1 - kt;
        if (rem >= 2) CPA_WAIT(2);
        else if (rem == 1) CPA_WAIT(1);
        else CPA_WAIT(0);
        __syncthreads();

        if (kt + 3 < KT) load_tile((kt + 3) & 3, kt + 3);

        const uint32_t so = (kt & 3) * 55296u;

        uint32_t a[2][4][4];    // a: double-buffered across ks (32 regs)
        uint32_t b[2][4];       // b: double-buffered across p-groups (8 regs)
        // prime: a for ks=0 (all 4), b for (ks=0, p=0)
#pragma unroll
        for (int mi = 0; mi < 4; mi++) LDSM4(a[0][mi], aB[mi] + so);
        LDSM4(b[0], bB[0] + so);

#pragma unroll
        for (int ks = 0; ks < 4; ks++) {
            const int ca = ks & 1;
#pragma unroll
            for (int p = 0; p < 4; p++) {
                const int cb = (ks * 4 + p) & 1;
                const int nb = cb ^ 1;
                // prefetch next b one p-group ahead
                if (p < 3)       LDSM4(b[nb], bB[p + 1] + so + ks * 32);
                else if (ks < 3) LDSM4(b[nb], bB[0]     + so + (ks + 1) * 32);
                // spread next-ks a prefetch: one LDSM4 per p-group
                if (ks < 3)      LDSM4(a[ca ^ 1][p], aB[p] + so + (ks + 1) * 32);
                // 8 MMAs for this p-group
#pragma unroll
                for (int mi = 0; mi < 4; mi++) {
                    mma8(acc[mi][2 * p],     a[ca][mi], &b[cb][0]);
                    mma8(acc[mi][2 * p + 1], a[ca][mi], &b[cb][2]);
                }
            }
        }
    }

    // epilogue
#pragma unroll
    for (int mi = 0; mi < 4; mi++) {
        const int row = t0 + warpM * 64 + mi * 16 + (lane >> 2);
#pragma unroll
        for (int ni = 0; ni < 8; ni++) {
            const int col = n0 + warpN * 64 + ni * 8 + ((lane & 3) << 1);
            if (col < N) {   // N even -> col+1 also valid
                epi_store(epi, C, C2, row,     col,     acc[mi][ni][0]);
                epi_store(epi, C, C2, row,     col + 1, acc[mi][ni][1]);
                epi_store(epi, C, C2, row + 8, col,     acc[mi][ni][2]);
                epi_store(epi, C, C2, row + 8, col + 1, acc[mi][ni][3]);
            }
        }
    }
}

// down-projection: [qa | ckv] = hidden(raw f32, HW-truncated) @ w12^T
__global__ void __launch_bounds__(256, 1)
gemm_down(const float* __restrict__ A, const float* __restrict__ W,
          float* __restrict__ C, float* __restrict__ C2)
{
    extern __shared__ float smem[];
    gemm_core(A, W, C, C2, 2112, 4096, blockIdx.y * 128, blockIdx.x * 256, 3, smem);
}

// merged up-projections: blocks [0,24) = query (K=1536), [24,56) = kv (K=512)
__global__ void __launch_bounds__(256, 1)
gemm_up(const float* __restrict__ Aq, const float* __restrict__ Wq,
        const float* __restrict__ Akv, const float* __restrict__ Wkv,
        float* __restrict__ out)
{
    extern __shared__ float smem[];
    const int bx = blockIdx.x;
    const int t0 = blockIdx.y * 128;
    if (bx < 24)
        gemm_core(Aq,  Wq,  out, nullptr, 6144, 1536, t0, bx * 256, 1, smem);
    else
        gemm_core(Akv, Wkv, out, nullptr, 8192, 512,  t0, (bx - 24) * 256, 2, smem);
}

// ---------------------------------------------------------------------------
// merged f32 -> tf32(rna) conversion of all four weight tensors
// ---------------------------------------------------------------------------
#define N4_0 1572864   // q_a_w  /4
#define N4_1 589824    // kv_a_w /4
#define N4_2 2359296   // q_b_w  /4
#define N4_3 1048576   // kv_b_w /4

__device__ __forceinline__ float4 cv4(float4 v) {
    v.x = __uint_as_float(f2tf(v.x));
    v.y = __uint_as_float(f2tf(v.y));
    v.z = __uint_as_float(f2tf(v.z));
    v.w = __uint_as_float(f2tf(v.w));
    return v;
}

__global__ void conv_all(const float4* __restrict__ s0, float4* __restrict__ d0,
                         const float4* __restrict__ s1, float4* __restrict__ d1,
                         const float4* __restrict__ s2, float4* __restrict__ d2,
                         const float4* __restrict__ s3, float4* __restrict__ d3)
{
    int i = blockIdx.x * blockDim.x + threadIdx.x;
    if (i < N4_0) { d0[i] = cv4(s0[i]); return; }
    i -= N4_0;
    if (i < N4_1) { d1[i] = cv4(s1[i]); return; }
    i -= N4_1;
    if (i < N4_2) { d2[i] = cv4(s2[i]); return; }
    i -= N4_2;
    if (i < N4_3) { d3[i] = cv4(s3[i]); }
}

// ---------------------------------------------------------------------------
// merged norms: blocks [0,8192) rms(qa); [8192,16384) rms(ckv)+kpe+vpad
// ---------------------------------------------------------------------------
__device__ __forceinline__ float block_sum_256(float v) {
    __shared__ float red[8];
#pragma unroll
    for (int o = 16; o; o >>= 1) v += __shfl_xor_sync(0xffffffffu, v, o);
    const int w = threadIdx.x >> 5, l = threadIdx.x & 31;
    if (l == 0) red[w] = v;
    __syncthreads();
    float r = 0.f;
    if (w == 0) {
        r = (l < 8) ? red[l] : 0.f;
#pragma unroll
        for (int o = 4; o; o >>= 1) r += __shfl_xor_sync(0xffffffffu, r, o);
    }
    return r;
}

__global__ void rms_all(const float* __restrict__ qa, float* __restrict__ qat,
                        const float* __restrict__ qw,
                        const float* __restrict__ ckv, float* __restrict__ ckvnt,
                        const float* __restrict__ kw, float* __restrict__ out)
{
    __shared__ float s_sc;
    const int bid = blockIdx.x;
    if (bid < TOKENS) {
        const float* row = qa + (size_t)bid * 1536;
        float* dst       = qat + (size_t)bid * 1536;
        float ss = 0.f;
        for (int j = threadIdx.x; j < 1536; j += 256) { const float v = row[j]; ss += v * v; }
        const float tot = block_sum_256(ss);
        if (threadIdx.x == 0) s_sc = rsqrtf(tot / 1536.f + 1e-6f);
        __syncthreads();
        const float sc = s_sc;
        for (int j = threadIdx.x; j < 1536; j += 256)
            dst[j] = __uint_as_float(f2tf(row[j] * sc * qw[j]));
    } else {
        const int t = bid - TOKENS;
        const float* row = ckv + (size_t)t * 576;
        float ss = 0.f;
        for (int j = threadIdx.x; j < R_KV; j += 256) { const float v = row[j]; ss += v * v; }
        const float tot = block_sum_256(ss);
        if (threadIdx.x == 0) s_sc = rsqrtf(tot / (float)R_KV + 1e-6f);
        __syncthreads();
        const float sc = s_sc;
        for (int j = threadIdx.x; j < R_KV; j += 256)
            ckvnt[(size_t)t * R_KV + j] = __uint_as_float(f2tf(row[j] * sc * kw[j]));

        const int b = t >> 12;
        const int s = t & (SEQ - 1);
        // k_pe scatter (raw f32, deepseek-transposed) to all 32 key heads
        {
            const int j  = threadIdx.x & 63;
            const int hg = threadIdx.x >> 6;
            const float v = row[R_KV + j];
            const int col = D_NOPE + (j >> 1) + ((j & 1) << 5);
#pragma unroll
            for (int hh = 0; hh < 8; hh++) {
                const int h = hg * 8 + hh;
                out[((size_t)((b * OUT_CH + NHEAD + h) * SEQ + s)) * D_Q + col] = v;
            }
        }
        // value padding zero: out[b, 64+h, s, 128:192]
#pragma unroll
        for (int i = 0; i < 2; i++) {
            const int idx = threadIdx.x + i * 256;   // 0..511
            const int h = idx >> 4, f = idx & 15;
            float4* p = (float4*)(out + ((size_t)((b * OUT_CH + 2 * NHEAD + h) * SEQ + s)) * D_Q + D_NOPE) + f;
            *p = make_float4(0.f, 0.f, 0.f, 0.f);
        }
    }
}

// ---------------------------------------------------------------------------
extern "C" void kernel_launch(void* const* d_in, const int* in_sizes, int n_in,
                              void* d_out, int out_size)
{
    const float* hidden    = (const float*)d_in[0];
    const float* q_a_w     = (const float*)d_in[1];
    const float* q_b_w     = (const float*)d_in[2];
    const float* kv_a_w    = (const float*)d_in[3];
    const float* kv_b_w    = (const float*)d_in[4];
    const float* q_a_ln_w  = (const float*)d_in[5];
    const float* kv_a_ln_w = (const float*)d_in[6];
    float* out = (float*)d_out;

    float *w12, *w3, *w4, *qa, *qat, *ckv, *ckvnt;
    cudaGetSymbolAddress((void**)&w12,   g_w12);
    cudaGetSymbolAddress((void**)&w3,    g_w3);
    cudaGetSymbolAddress((void**)&w4,    g_w4);
    cudaGetSymbolAddress((void**)&qa,    g_qa);
    cudaGetSymbolAddress((void**)&qat,   g_qat);
    cudaGetSymbolAddress((void**)&ckv,   g_ckv);
    cudaGetSymbolAddress((void**)&ckvnt, g_ckvnt);

    const int SMEM = 4 * 13824 * 4;   // 221184 B
    cudaFuncSetAttribute(gemm_down, cudaFuncAttributeMaxDynamicSharedMemorySize, SMEM);
    cudaFuncSetAttribute(gemm_up,   cudaFuncAttributeMaxDynamicSharedMemorySize, SMEM);

    // 1) rna-convert all weights in one launch (hidden stays raw: HW truncates)
    {
        const int total = N4_0 + N4_1 + N4_2 + N4_3;
        conv_all<<<(total + 255) / 256, 256>>>(
            (const float4*)q_a_w,  (float4*)w12,
            (const float4*)kv_a_w, (float4*)(w12 + 6291456),
            (const float4*)q_b_w,  (float4*)w3,
            (const float4*)kv_b_w, (float4*)w4);
    }

    const dim3 blk(256);

    // 2) merged down-projection: [qa | ckv] = hidden @ [q_a_w | kv_a_w]^T
    gemm_down<<<dim3(9, 64), blk, SMEM>>>(hidden, w12, qa, ckv);

    // 3) merged norms + k_pe scatter + value padding
    rms_all<<<2 * TOKENS, 256>>>(qa, qat, q_a_ln_w, ckv, ckvnt, kv_a_ln_w, out);

    // 4) merged up-projections with fused scatter epilogues
    gemm_up<<<dim3(56, 64), blk, SMEM>>>(qat, w3, ckvnt, w4, out);
}

// round 14
// speedup vs baseline: 1.0757x; 1.0742x over previous
#include <cuda_runtime.h>
#include <cstdint>

// ---------------------------------------------------------------------------
// MLA QKV projection — R14: occupancy-doubled mma.sync TF32.
//   Block 128(tok) x 128(feat), warp tile 64x32, __launch_bounds__(256,2)
//   -> 2 CTAs/SM, 4 warps/SMSP (R12/R13 proved 2 warps/SMSP caps tensor at 54%).
//   3-stage BK=32 cp.async ring (110592 B/CTA; 2 CTAs = 216 KB/SM).
//   Hidden read raw (HW tf32 truncation); weights/activations rna-converted.
// ---------------------------------------------------------------------------

#define TOKENS   8192
#define SEQ      4096
#define NHEAD    32
#define D_Q      192
#define D_NOPE   128
#define R_KV     512
#define OUT_CH   96

// ---------------- scratch (__device__ globals; no allocs allowed) ----------
__device__ float g_w12  [8650752];    // [q_a_w | kv_a_w] tf32 (2112*4096)
__device__ float g_w3   [9437184];    // q_b_w   tf32  (6144*1536)
__device__ float g_w4   [4194304];    // kv_b_w  tf32  (8192*512)
__device__ float g_qa   [12582912];   // f32 down-proj out (8192*1536)
__device__ float g_qat  [12582912];   // tf32 normed qa
__device__ float g_ckv  [4718592];    // f32 down-proj out (8192*576)
__device__ float g_ckvnt[4194304];    // tf32 normed ckv (8192*512)

__device__ __forceinline__ uint32_t f2tf(float f) {
    uint32_t r; asm("cvt.rna.tf32.f32 %0, %1;" : "=r"(r) : "f"(f)); return r;
}

__device__ __forceinline__ void mma8(float c[4], const uint32_t a[4], const uint32_t b[2]) {
    asm volatile(
        "mma.sync.aligned.m16n8k8.row.col.f32.tf32.tf32.f32 "
        "{%0,%1,%2,%3},{%4,%5,%6,%7},{%8,%9},{%0,%1,%2,%3};"
        : "+f"(c[0]), "+f"(c[1]), "+f"(c[2]), "+f"(c[3])
        : "r"(a[0]), "r"(a[1]), "r"(a[2]), "r"(a[3]), "r"(b[0]), "r"(b[1]));
}

#define LDSM4(r, addr) \
    asm volatile("ldmatrix.sync.aligned.m8n8.x4.shared.b16 {%0,%1,%2,%3}, [%4];" \
        : "=r"((r)[0]), "=r"((r)[1]), "=r"((r)[2]), "=r"((r)[3]) : "r"(addr))

__device__ __forceinline__ void cpa16(uint32_t dst, const void* src, int nbytes) {
    asm volatile("cp.async.cg.shared.global [%0], [%1], 16, %2;"
                 :: "r"(dst), "l"(src), "r"(nbytes));
}
#define CPA_COMMIT() asm volatile("cp.async.commit_group;" ::: "memory")
#define CPA_WAIT(n)  asm volatile("cp.async.wait_group %0;" :: "n"(n) : "memory")

// epi modes: 1 = query scatter, 2 = key/value scatter, 3 = down (qa|ckv split)
__device__ __forceinline__ void epi_store(int epi, float* __restrict__ C,
                                          float* __restrict__ C2, int t, int n, float v) {
    if (epi == 3) {
        if (n < 1536) C [(size_t)t * 1536 + n] = v;
        else          C2[(size_t)t * 576 + (n - 1536)] = v;
        return;
    }
    const int b = t >> 12;
    const int s = t & (SEQ - 1);
    if (epi == 1) {
        const int h = n / D_Q;
        const int d = n - h * D_Q;
        int col;
        if (d < D_NOPE) col = d;
        else {
            const int j = d - D_NOPE;
            col = D_NOPE + (j >> 1) + ((j & 1) << 5);
        }
        C[((size_t)((b * OUT_CH + h) * SEQ + s)) * D_Q + col] = v;
    } else {
        const int h  = n >> 8;
        const int d  = n & 255;
        const int ch = (d < 128) ? (NHEAD + h) : (2 * NHEAD + h);
        C[((size_t)((b * OUT_CH + ch) * SEQ + s)) * D_Q + (d & 127)] = v;
    }
}

// ---------------------------------------------------------------------------
// GEMM core: C = A[M,K](tokens) * W[N,K]^T(features)
// BM=128, BN=128, BK=32; 256 threads = 8 warps (2x4), warp tile 64x32.
// smem row stride 36; stage = 9216 floats (36864 B); 3 stages = 110592 B.
// ---------------------------------------------------------------------------
__device__ __forceinline__ void
gemm_core(const float* __restrict__ A, const float* __restrict__ W,
          float* __restrict__ C, float* __restrict__ C2,
          int N, int K, int t0, int n0, int epi, float* smem)
{
    const int tid   = threadIdx.x;
    const int lane  = tid & 31;
    const int wrp   = tid >> 5;
    const int warpM = wrp >> 2;            // 0..1 -> 64 token rows
    const int warpN = wrp & 3;             // 0..3 -> 32 feature cols

    float acc[4][4][4];
#pragma unroll
    for (int i = 0; i < 4; i++)
#pragma unroll
        for (int j = 0; j < 4; j++)
#pragma unroll
            for (int k = 0; k < 4; k++) acc[i][j][k] = 0.f;

    const int KT = K >> 5;

    auto load_tile = [&](int s, int kt) {
        const int kk = kt * 32;
        float* sA = smem + s * 9216;
        float* sB = sA + 4608;
        // A: 128 rows x 32 -> 1024 float4, 4 per thread
#pragma unroll
        for (int i = 0; i < 4; i++) {
            const int f = tid + i * 256;
            const int row = f >> 3, cq = (f & 7) << 2;
            const uint32_t dst = (uint32_t)__cvta_generic_to_shared(sA + row * 36 + cq);
            cpa16(dst, A + (size_t)(t0 + row) * K + kk + cq, 16);
        }
        // B: 128 rows x 32 -> 1024 float4, 4 per thread (zero-fill past N)
#pragma unroll
        for (int i = 0; i < 4; i++) {
            const int f = tid + i * 256;
            const int row = f >> 3, cq = (f & 7) << 2;
            const int gn = n0 + row;
            const uint32_t dst = (uint32_t)__cvta_generic_to_shared(sB + row * 36 + cq);
            const int ok = (gn < N) ? 16 : 0;
            cpa16(dst, W + (size_t)(ok ? gn : 0) * K + kk + cq, ok);
        }
        CPA_COMMIT();
    };

    load_tile(0, 0);
    if (KT > 1) load_tile(1, 1);

    // hoisted LDSM base addresses (stage 0, byte offsets)
    const uint32_t sb0 = (uint32_t)__cvta_generic_to_shared(smem);
    const int lm = lane >> 3;
    const int lr = lane & 7;
    const int ar = warpM * 64 + (lm & 1) * 8 + lr;
    const int ak = (lm >> 1) * 4;
    const int br = warpN * 32 + (lm >> 1) * 8 + lr;
    const int bk = (lm & 1) * 4;
    uint32_t aB[4], bB[2];
#pragma unroll
    for (int mi = 0; mi < 4; mi++) aB[mi] = sb0 + ((ar + mi * 16) * 36 + ak) * 4;
#pragma unroll
    for (int p = 0; p < 2; p++)   bB[p]  = sb0 + ((4608 + (br + p * 16) * 36 + bk)) * 4;

    for (int kt = 0; kt < KT; kt++) {
        if (kt + 1 < KT) CPA_WAIT(1); else CPA_WAIT(0);
        __syncthreads();

        if (kt + 2 < KT) load_tile((kt + 2) % 3, kt + 2);

        const uint32_t so = (kt % 3) * 36864u;

#pragma unroll
        for (int ks = 0; ks < 4; ks++) {
            const uint32_t o = so + ks * 32;
            uint32_t a[4][4], b[2][4];
#pragma unroll
            for (int mi = 0; mi < 4; mi++) LDSM4(a[mi], aB[mi] + o);
#pragma unroll
            for (int p = 0; p < 2; p++)   LDSM4(b[p],  bB[p]  + o);
#pragma unroll
            for (int mi = 0; mi < 4; mi++)
#pragma unroll
                for (int p = 0; p < 2; p++) {
                    mma8(acc[mi][2 * p],     a[mi], &b[p][0]);
                    mma8(acc[mi][2 * p + 1], a[mi], &b[p][2]);
                }
        }
        __syncthreads();
    }

    // epilogue
#pragma unroll
    for (int mi = 0; mi < 4; mi++) {
        const int row = t0 + warpM * 64 + mi * 16 + (lane >> 2);
#pragma unroll
        for (int ni = 0; ni < 4; ni++) {
            const int col = n0 + warpN * 32 + ni * 8 + ((lane & 3) << 1);
            if (col < N) {   // N even -> col+1 also valid
                epi_store(epi, C, C2, row,     col,     acc[mi][ni][0]);
                epi_store(epi, C, C2, row,     col + 1, acc[mi][ni][1]);
                epi_store(epi, C, C2, row + 8, col,     acc[mi][ni][2]);
                epi_store(epi, C, C2, row + 8, col + 1, acc[mi][ni][3]);
            }
        }
    }
}

// down-projection: [qa | ckv] = hidden(raw f32, HW-truncated) @ w12^T
__global__ void __launch_bounds__(256, 2)
gemm_down(const float* __restrict__ A, const float* __restrict__ W,
          float* __restrict__ C, float* __restrict__ C2)
{
    extern __shared__ float smem[];
    gemm_core(A, W, C, C2, 2112, 4096, blockIdx.y * 128, blockIdx.x * 128, 3, smem);
}

// merged up-projections: blocks [0,48) = query (K=1536), [48,112) = kv (K=512)
__global__ void __launch_bounds__(256, 2)
gemm_up(const float* __restrict__ Aq, const float* __restrict__ Wq,
        const float* __restrict__ Akv, const float* __restrict__ Wkv,
        float* __restrict__ out)
{
    extern __shared__ float smem[];
    const int bx = blockIdx.x;
    const int t0 = blockIdx.y * 128;
    if (bx < 48)
        gemm_core(Aq,  Wq,  out, nullptr, 6144, 1536, t0, bx * 128, 1, smem);
    else
        gemm_core(Akv, Wkv, out, nullptr, 8192, 512,  t0, (bx - 48) * 128, 2, smem);
}

// ---------------------------------------------------------------------------
// merged f32 -> tf32(rna) conversion of all four weight tensors
// ---------------------------------------------------------------------------
#define N4_0 1572864   // q_a_w  /4
#define N4_1 589824    // kv_a_w /4
#define N4_2 2359296   // q_b_w  /4
#define N4_3 1048576   // kv_b_w /4

__device__ __forceinline__ float4 cv4(float4 v) {
    v.x = __uint_as_float(f2tf(v.x));
    v.y = __uint_as_float(f2tf(v.y));
    v.z = __uint_as_float(f2tf(v.z));
    v.w = __uint_as_float(f2tf(v.w));
    return v;
}

__global__ void conv_all(const float4* __restrict__ s0, float4* __restrict__ d0,
                         const float4* __restrict__ s1, float4* __restrict__ d1,
                         const float4* __restrict__ s2, float4* __restrict__ d2,
                         const float4* __restrict__ s3, float4* __restrict__ d3)
{
    int i = blockIdx.x * blockDim.x + threadIdx.x;
    if (i < N4_0) { d0[i] = cv4(s0[i]); return; }
    i -= N4_0;
    if (i < N4_1) { d1[i] = cv4(s1[i]); return; }
    i -= N4_1;
    if (i < N4_2) { d2[i] = cv4(s2[i]); return; }
    i -= N4_2;
    if (i < N4_3) { d3[i] = cv4(s3[i]); }
}

// ---------------------------------------------------------------------------
// merged norms: blocks [0,8192) rms(qa); [8192,16384) rms(ckv)+kpe+vpad
// ---------------------------------------------------------------------------
__device__ __forceinline__ float block_sum_256(float v) {
    __shared__ float red[8];
#pragma unroll
    for (int o = 16; o; o >>= 1) v += __shfl_xor_sync(0xffffffffu, v, o);
    const int w = threadIdx.x >> 5, l = threadIdx.x & 31;
    if (l == 0) red[w] = v;
    __syncthreads();
    float r = 0.f;
    if (w == 0) {
        r = (l < 8) ? red[l] : 0.f;
#pragma unroll
        for (int o = 4; o; o >>= 1) r += __shfl_xor_sync(0xffffffffu, r, o);
    }
    return r;
}

__global__ void rms_all(const float* __restrict__ qa, float* __restrict__ qat,
                        const float* __restrict__ qw,
                        const float* __restrict__ ckv, float* __restrict__ ckvnt,
                        const float* __restrict__ kw, float* __restrict__ out)
{
    __shared__ float s_sc;
    const int bid = blockIdx.x;
    if (bid < TOKENS) {
        const float* row = qa + (size_t)bid * 1536;
        float* dst       = qat + (size_t)bid * 1536;
        float ss = 0.f;
        for (int j = threadIdx.x; j < 1536; j += 256) { const float v = row[j]; ss += v * v; }
        const float tot = block_sum_256(ss);
        if (threadIdx.x == 0) s_sc = rsqrtf(tot / 1536.f + 1e-6f);
        __syncthreads();
        const float sc = s_sc;
        for (int j = threadIdx.x; j < 1536; j += 256)
            dst[j] = __uint_as_float(f2tf(row[j] * sc * qw[j]));
    } else {
        const int t = bid - TOKENS;
        const float* row = ckv + (size_t)t * 576;
        float ss = 0.f;
        for (int j = threadIdx.x; j < R_KV; j += 256) { const float v = row[j]; ss += v * v; }
        const float tot = block_sum_256(ss);
        if (threadIdx.x == 0) s_sc = rsqrtf(tot / (float)R_KV + 1e-6f);
        __syncthreads();
        const float sc = s_sc;
        for (int j = threadIdx.x; j < R_KV; j += 256)
            ckvnt[(size_t)t * R_KV + j] = __uint_as_float(f2tf(row[j] * sc * kw[j]));

        const int b = t >> 12;
        const int s = t & (SEQ - 1);
        // k_pe scatter (raw f32, deepseek-transposed) to all 32 key heads
        {
            const int j  = threadIdx.x & 63;
            const int hg = threadIdx.x >> 6;
            const float v = row[R_KV + j];
            const int col = D_NOPE + (j >> 1) + ((j & 1) << 5);
#pragma unroll
            for (int hh = 0; hh < 8; hh++) {
                const int h = hg * 8 + hh;
                out[((size_t)((b * OUT_CH + NHEAD + h) * SEQ + s)) * D_Q + col] = v;
            }
        }
        // value padding zero: out[b, 64+h, s, 128:192]
#pragma unroll
        for (int i = 0; i < 2; i++) {
            const int idx = threadIdx.x + i * 256;   // 0..511
            const int h = idx >> 4, f = idx & 15;
            float4* p = (float4*)(out + ((size_t)((b * OUT_CH + 2 * NHEAD + h) * SEQ + s)) * D_Q + D_NOPE) + f;
            *p = make_float4(0.f, 0.f, 0.f, 0.f);
        }
    }
}

// ---------------------------------------------------------------------------
extern "C" void kernel_launch(void* const* d_in, const int* in_sizes, int n_in,
                              void* d_out, int out_size)
{
    const float* hidden    = (const float*)d_in[0];
    const float* q_a_w     = (const float*)d_in[1];
    const float* q_b_w     = (const float*)d_in[2];
    const float* kv_a_w    = (const float*)d_in[3];
    const float* kv_b_w    = (const float*)d_in[4];
    const float* q_a_ln_w  = (const float*)d_in[5];
    const float* kv_a_ln_w = (const float*)d_in[6];
    float* out = (float*)d_out;

    float *w12, *w3, *w4, *qa, *qat, *ckv, *ckvnt;
    cudaGetSymbolAddress((void**)&w12,   g_w12);
    cudaGetSymbolAddress((void**)&w3,    g_w3);
    cudaGetSymbolAddress((void**)&w4,    g_w4);
    cudaGetSymbolAddress((void**)&qa,    g_qa);
    cudaGetSymbolAddress((void**)&qat,   g_qat);
    cudaGetSymbolAddress((void**)&ckv,   g_ckv);
    cudaGetSymbolAddress((void**)&ckvnt, g_ckvnt);

    const int SMEM = 3 * 9216 * 4;   // 110592 B per CTA (2 CTAs/SM)
    cudaFuncSetAttribute(gemm_down, cudaFuncAttributeMaxDynamicSharedMemorySize, SMEM);
    cudaFuncSetAttribute(gemm_up,   cudaFuncAttributeMaxDynamicSharedMemorySize, SMEM);

    // 1) rna-convert all weights in one launch (hidden stays raw: HW truncates)
    {
        const int total = N4_0 + N4_1 + N4_2 + N4_3;
        conv_all<<<(total + 255) / 256, 256>>>(
            (const float4*)q_a_w,  (float4*)w12,
            (const float4*)kv_a_w, (float4*)(w12 + 6291456),
            (const float4*)q_b_w,  (float4*)w3,
            (const float4*)kv_b_w, (float4*)w4);
    }

    const dim3 blk(256);

    // 2) merged down-projection: [qa | ckv] = hidden @ [q_a_w | kv_a_w]^T
    //    N=2112 -> 17 x-tiles (last half-tile guarded by col<N)
    gemm_down<<<dim3(17, 64), blk, SMEM>>>(hidden, w12, qa, ckv);

    // 3) merged norms + k_pe scatter + value padding
    rms_all<<<2 * TOKENS, 256>>>(qa, qat, q_a_ln_w, ckv, ckvnt, kv_a_ln_w, out);

    // 4) merged up-projections with fused scatter epilogues
    gemm_up<<<dim3(112, 64), blk, SMEM>>>(qat, w3, ckvnt, w4, out);
}

// round 16
// speedup vs baseline: 1.0869x; 1.0104x over previous
#include <cuda_runtime.h>
#include <cstdint>

// ---------------------------------------------------------------------------
// MLA QKV projection — R16: fix R15's pipeline race (2-stage ring was
// prefetching kt+2 into the stage being read). Schedule is now
//   wait -> sync -> compute -> sync -> prefetch   (R7-proven for 2 stages).
//   Block 128(tok) x 192(feat), warp tile 64x48, __launch_bounds__(256,2),
//   2 CTAs/SM, 92160 B/CTA smem, mi-sequential inner loop (~124 regs).
//   Hidden read raw (HW tf32 truncation); weights/activations rna-converted.
// ---------------------------------------------------------------------------

#define TOKENS   8192
#define SEQ      4096
#define NHEAD    32
#define D_Q      192
#define D_NOPE   128
#define R_KV     512
#define OUT_CH   96

// ---------------- scratch (__device__ globals; no allocs allowed) ----------
__device__ float g_w12  [8650752];    // [q_a_w | kv_a_w] tf32 (2112*4096)
__device__ float g_w3   [9437184];    // q_b_w   tf32  (6144*1536)
__device__ float g_w4   [4194304];    // kv_b_w  tf32  (8192*512)
__device__ float g_qa   [12582912];   // f32 down-proj out (8192*1536)
__device__ float g_qat  [12582912];   // tf32 normed qa
__device__ float g_ckv  [4718592];    // f32 down-proj out (8192*576)
__device__ float g_ckvnt[4194304];    // tf32 normed ckv (8192*512)

__device__ __forceinline__ uint32_t f2tf(float f) {
    uint32_t r; asm("cvt.rna.tf32.f32 %0, %1;" : "=r"(r) : "f"(f)); return r;
}

__device__ __forceinline__ void mma8(float c[4], const uint32_t a[4], const uint32_t b[2]) {
    asm volatile(
        "mma.sync.aligned.m16n8k8.row.col.f32.tf32.tf32.f32 "
        "{%0,%1,%2,%3},{%4,%5,%6,%7},{%8,%9},{%0,%1,%2,%3};"
        : "+f"(c[0]), "+f"(c[1]), "+f"(c[2]), "+f"(c[3])
        : "r"(a[0]), "r"(a[1]), "r"(a[2]), "r"(a[3]), "r"(b[0]), "r"(b[1]));
}

#define LDSM4(r, addr) \
    asm volatile("ldmatrix.sync.aligned.m8n8.x4.shared.b16 {%0,%1,%2,%3}, [%4];" \
        : "=r"((r)[0]), "=r"((r)[1]), "=r"((r)[2]), "=r"((r)[3]) : "r"(addr))

__device__ __forceinline__ void cpa16(uint32_t dst, const void* src, int nbytes) {
    asm volatile("cp.async.cg.shared.global [%0], [%1], 16, %2;"
                 :: "r"(dst), "l"(src), "r"(nbytes));
}
#define CPA_COMMIT() asm volatile("cp.async.commit_group;" ::: "memory")
#define CPA_WAIT(n)  asm volatile("cp.async.wait_group %0;" :: "n"(n) : "memory")

// epi modes: 1 = query scatter, 2 = key/value scatter, 3 = down (qa|ckv split)
__device__ __forceinline__ void epi_store(int epi, float* __restrict__ C,
                                          float* __restrict__ C2, int t, int n, float v) {
    if (epi == 3) {
        if (n < 1536) C [(size_t)t * 1536 + n] = v;
        else          C2[(size_t)t * 576 + (n - 1536)] = v;
        return;
    }
    const int b = t >> 12;
    const int s = t & (SEQ - 1);
    if (epi == 1) {
        const int h = n / D_Q;
        const int d = n - h * D_Q;
        int col;
        if (d < D_NOPE) col = d;
        else {
            const int j = d - D_NOPE;
            col = D_NOPE + (j >> 1) + ((j & 1) << 5);
        }
        C[((size_t)((b * OUT_CH + h) * SEQ + s)) * D_Q + col] = v;
    } else {
        const int h  = n >> 8;
        const int d  = n & 255;
        const int ch = (d < 128) ? (NHEAD + h) : (2 * NHEAD + h);
        C[((size_t)((b * OUT_CH + ch) * SEQ + s)) * D_Q + (d & 127)] = v;
    }
}

// ---------------------------------------------------------------------------
// GEMM core: C = A[M,K](tokens) * W[N,K]^T(features)
// BM=128, BN=192, BK=32; 256 threads = 8 warps (2x4), warp tile 64x48.
// smem row stride 36; stage = 11520 floats (46080 B); 2 stages = 92160 B.
// Pipeline (2-stage-safe): wait -> sync -> compute -> sync -> prefetch kt+2.
// ---------------------------------------------------------------------------
__device__ __forceinline__ void
gemm_core(const float* __restrict__ A, const float* __restrict__ W,
          float* __restrict__ C, float* __restrict__ C2,
          int N, int K, int t0, int n0, int epi, float* smem)
{
    const int tid   = threadIdx.x;
    const int lane  = tid & 31;
    const int wrp   = tid >> 5;
    const int warpM = wrp >> 2;            // 0..1 -> 64 token rows
    const int warpN = wrp & 3;             // 0..3 -> 48 feature cols

    float acc[4][6][4];
#pragma unroll
    for (int i = 0; i < 4; i++)
#pragma unroll
        for (int j = 0; j < 6; j++)
#pragma unroll
            for (int k = 0; k < 4; k++) acc[i][j][k] = 0.f;

    const int KT = K >> 5;

    auto load_tile = [&](int s, int kt) {
        const int kk = kt * 32;
        float* sA = smem + s * 11520;
        float* sB = sA + 4608;
        // A: 128 rows x 32 -> 1024 float4, 4 per thread
#pragma unroll
        for (int i = 0; i < 4; i++) {
            const int f = tid + i * 256;
            const int row = f >> 3, cq = (f & 7) << 2;
            const uint32_t dst = (uint32_t)__cvta_generic_to_shared(sA + row * 36 + cq);
            cpa16(dst, A + (size_t)(t0 + row) * K + kk + cq, 16);
        }
        // B: 192 rows x 32 -> 1536 float4, 6 per thread (zero-fill past N)
#pragma unroll
        for (int i = 0; i < 6; i++) {
            const int f = tid + i * 256;
            const int row = f >> 3, cq = (f & 7) << 2;
            const int gn = n0 + row;
            const uint32_t dst = (uint32_t)__cvta_generic_to_shared(sB + row * 36 + cq);
            const int ok = (gn < N) ? 16 : 0;
            cpa16(dst, W + (size_t)(ok ? gn : 0) * K + kk + cq, ok);
        }
        CPA_COMMIT();
    };

    load_tile(0, 0);
    if (KT > 1) load_tile(1, 1);

    // hoisted LDSM base addresses (stage 0, byte offsets)
    const uint32_t sb0 = (uint32_t)__cvta_generic_to_shared(smem);
    const int lm = lane >> 3;
    const int lr = lane & 7;
    const int ar = warpM * 64 + (lm & 1) * 8 + lr;
    const int ak = (lm >> 1) * 4;
    const int br = warpN * 48 + (lm >> 1) * 8 + lr;
    const int bk = (lm & 1) * 4;
    uint32_t aB[4], bB[3];
#pragma unroll
    for (int mi = 0; mi < 4; mi++) aB[mi] = sb0 + ((ar + mi * 16) * 36 + ak) * 4;
#pragma unroll
    for (int p = 0; p < 3; p++)   bB[p]  = sb0 + ((4608 + (br + p * 16) * 36 + bk)) * 4;

    for (int kt = 0; kt < KT; kt++) {
        if (kt + 1 < KT) CPA_WAIT(1); else CPA_WAIT(0);
        __syncthreads();

        const uint32_t so = (kt & 1) * 46080u;

#pragma unroll
        for (int ks = 0; ks < 4; ks++) {
            const uint32_t o = so + ks * 32;
            uint32_t b[3][4];
#pragma unroll
            for (int p = 0; p < 3; p++) LDSM4(b[p], bB[p] + o);
            // mi-sequential: one a-LDSM, then 6 MMAs (covers next a's latency)
#pragma unroll
            for (int mi = 0; mi < 4; mi++) {
                uint32_t a[4];
                LDSM4(a, aB[mi] + o);
#pragma unroll
                for (int p = 0; p < 3; p++) {
                    mma8(acc[mi][2 * p],     a, &b[p][0]);
                    mma8(acc[mi][2 * p + 1], a, &b[p][2]);
                }
            }
        }
        __syncthreads();   // all warps done reading this stage
        if (kt + 2 < KT) load_tile(kt & 1, kt + 2);   // now safe to overwrite
    }

    // epilogue
#pragma unroll
    for (int mi = 0; mi < 4; mi++) {
        const int row = t0 + warpM * 64 + mi * 16 + (lane >> 2);
#pragma unroll
        for (int ni = 0; ni < 6; ni++) {
            const int col = n0 + warpN * 48 + ni * 8 + ((lane & 3) << 1);
            if (col < N) {   // N even -> col+1 also valid
                epi_store(epi, C, C2, row,     col,     acc[mi][ni][0]);
                epi_store(epi, C, C2, row,     col + 1, acc[mi][ni][1]);
                epi_store(epi, C, C2, row + 8, col,     acc[mi][ni][2]);
                epi_store(epi, C, C2, row + 8, col + 1, acc[mi][ni][3]);
            }
        }
    }
}

// down-projection: [qa | ckv] = hidden(raw f32, HW-truncated) @ w12^T
__global__ void __launch_bounds__(256, 2)
gemm_down(const float* __restrict__ A, const float* __restrict__ W,
          float* __restrict__ C, float* __restrict__ C2)
{
    extern __shared__ float smem[];
    gemm_core(A, W, C, C2, 2112, 4096, blockIdx.y * 128, blockIdx.x * 192, 3, smem);
}

// merged up-projections: blocks [0,32) = query (K=1536), [32,75) = kv (K=512)
__global__ void __launch_bounds__(256, 2)
gemm_up(const float* __restrict__ Aq, const float* __restrict__ Wq,
        const float* __restrict__ Akv, const float* __restrict__ Wkv,
        float* __restrict__ out)
{
    extern __shared__ float smem[];
    const int bx = blockIdx.x;
    const int t0 = blockIdx.y * 128;
    if (bx < 32)
        gemm_core(Aq,  Wq,  out, nullptr, 6144, 1536, t0, bx * 192, 1, smem);
    else
        gemm_core(Akv, Wkv, out, nullptr, 8192, 512,  t0, (bx - 32) * 192, 2, smem);
}

// ---------------------------------------------------------------------------
// merged f32 -> tf32(rna) conversion of all four weight tensors
// ---------------------------------------------------------------------------
#define N4_0 1572864   // q_a_w  /4
#define N4_1 589824    // kv_a_w /4
#define N4_2 2359296   // q_b_w  /4
#define N4_3 1048576   // kv_b_w /4

__device__ __forceinline__ float4 cv4(float4 v) {
    v.x = __uint_as_float(f2tf(v.x));
    v.y = __uint_as_float(f2tf(v.y));
    v.z = __uint_as_float(f2tf(v.z));
    v.w = __uint_as_float(f2tf(v.w));
    return v;
}

__global__ void conv_all(const float4* __restrict__ s0, float4* __restrict__ d0,
                         const float4* __restrict__ s1, float4* __restrict__ d1,
                         const float4* __restrict__ s2, float4* __restrict__ d2,
                         const float4* __restrict__ s3, float4* __restrict__ d3)
{
    int i = blockIdx.x * blockDim.x + threadIdx.x;
    if (i < N4_0) { d0[i] = cv4(s0[i]); return; }
    i -= N4_0;
    if (i < N4_1) { d1[i] = cv4(s1[i]); return; }
    i -= N4_1;
    if (i < N4_2) { d2[i] = cv4(s2[i]); return; }
    i -= N4_2;
    if (i < N4_3) { d3[i] = cv4(s3[i]); }
}

// ---------------------------------------------------------------------------
// merged norms: blocks [0,8192) rms(qa); [8192,16384) rms(ckv)+kpe+vpad
// ---------------------------------------------------------------------------
__device__ __forceinline__ float block_sum_256(float v) {
    __shared__ float red[8];
#pragma unroll
    for (int o = 16; o; o >>= 1) v += __shfl_xor_sync(0xffffffffu, v, o);
    const int w = threadIdx.x >> 5, l = threadIdx.x & 31;
    if (l == 0) red[w] = v;
    __syncthreads();
    float r = 0.f;
    if (w == 0) {
        r = (l < 8) ? red[l] : 0.f;
#pragma unroll
        for (int o = 4; o; o >>= 1) r += __shfl_xor_sync(0xffffffffu, r, o);
    }
    return r;
}

__global__ void rms_all(const float* __restrict__ qa, float* __restrict__ qat,
                        const float* __restrict__ qw,
                        const float* __restrict__ ckv, float* __restrict__ ckvnt,
                        const float* __restrict__ kw, float* __restrict__ out)
{
    __shared__ float s_sc;
    const int bid = blockIdx.x;
    if (bid < TOKENS) {
        const float* row = qa + (size_t)bid * 1536;
        float* dst       = qat + (size_t)bid * 1536;
        float ss = 0.f;
        for (int j = threadIdx.x; j < 1536; j += 256) { const float v = row[j]; ss += v * v; }
        const float tot = block_sum_256(ss);
        if (threadIdx.x == 0) s_sc = rsqrtf(tot / 1536.f + 1e-6f);
        __syncthreads();
        const float sc = s_sc;
        for (int j = threadIdx.x; j < 1536; j += 256)
            dst[j] = __uint_as_float(f2tf(row[j] * sc * qw[j]));
    } else {
        const int t = bid - TOKENS;
        const float* row = ckv + (size_t)t * 576;
        float ss = 0.f;
        for (int j = threadIdx.x; j < R_KV; j += 256) { const float v = row[j]; ss += v * v; }
        const float tot = block_sum_256(ss);
        if (threadIdx.x == 0) s_sc = rsqrtf(tot / (float)R_KV + 1e-6f);
        __syncthreads();
        const float sc = s_sc;
        for (int j = threadIdx.x; j < R_KV; j += 256)
            ckvnt[(size_t)t * R_KV + j] = __uint_as_float(f2tf(row[j] * sc * kw[j]));

        const int b = t >> 12;
        const int s = t & (SEQ - 1);
        // k_pe scatter (raw f32, deepseek-transposed) to all 32 key heads
        {
            const int j  = threadIdx.x & 63;
            const int hg = threadIdx.x >> 6;
            const float v = row[R_KV + j];
            const int col = D_NOPE + (j >> 1) + ((j & 1) << 5);
#pragma unroll
            for (int hh = 0; hh < 8; hh++) {
                const int h = hg * 8 + hh;
                out[((size_t)((b * OUT_CH + NHEAD + h) * SEQ + s)) * D_Q + col] = v;
            }
        }
        // value padding zero: out[b, 64+h, s, 128:192]
#pragma unroll
        for (int i = 0; i < 2; i++) {
            const int idx = threadIdx.x + i * 256;   // 0..511
            const int h = idx >> 4, f = idx & 15;
            float4* p = (float4*)(out + ((size_t)((b * OUT_CH + 2 * NHEAD + h) * SEQ + s)) * D_Q + D_NOPE) + f;
            *p = make_float4(0.f, 0.f, 0.f, 0.f);
        }
    }
}

// ---------------------------------------------------------------------------
extern "C" void kernel_launch(void* const* d_in, const int* in_sizes, int n_in,
                              void* d_out, int out_size)
{
    const float* hidden    = (const float*)d_in[0];
    const float* q_a_w     = (const float*)d_in[1];
    const float* q_b_w     = (const float*)d_in[2];
    const float* kv_a_w    = (const float*)d_in[3];
    const float* kv_b_w    = (const float*)d_in[4];
    const float* q_a_ln_w  = (const float*)d_in[5];
    const float* kv_a_ln_w = (const float*)d_in[6];
    float* out = (float*)d_out;

    float *w12, *w3, *w4, *qa, *qat, *ckv, *ckvnt;
    cudaGetSymbolAddress((void**)&w12,   g_w12);
    cudaGetSymbolAddress((void**)&w3,    g_w3);
    cudaGetSymbolAddress((void**)&w4,    g_w4);
    cudaGetSymbolAddress((void**)&qa,    g_qa);
    cudaGetSymbolAddress((void**)&qat,   g_qat);
    cudaGetSymbolAddress((void**)&ckv,   g_ckv);
    cudaGetSymbolAddress((void**)&ckvnt, g_ckvnt);

    const int SMEM = 2 * 11520 * 4;   // 92160 B per CTA (2 CTAs/SM)
    cudaFuncSetAttribute(gemm_down, cudaFuncAttributeMaxDynamicSharedMemorySize, SMEM);
    cudaFuncSetAttribute(gemm_up,   cudaFuncAttributeMaxDynamicSharedMemorySize, SMEM);

    // 1) rna-convert all weights in one launch (hidden stays raw: HW truncates)
    {
        const int total = N4_0 + N4_1 + N4_2 + N4_3;
        conv_all<<<(total + 255) / 256, 256>>>(
            (const float4*)q_a_w,  (float4*)w12,
            (const float4*)kv_a_w, (float4*)(w12 + 6291456),
            (const float4*)q_b_w,  (float4*)w3,
            (const float4*)kv_b_w, (float4*)w4);
    }

    const dim3 blk(256);

    // 2) merged down-projection: [qa | ckv] = hidden @ [q_a_w | kv_a_w]^T
    //    N=2112 = 11 x 192 exactly
    gemm_down<<<dim3(11, 64), blk, SMEM>>>(hidden, w12, qa, ckv);

    // 3) merged norms + k_pe scatter + value padding
    rms_all<<<2 * TOKENS, 256>>>(qa, qat, q_a_ln_w, ckv, ckvnt, kv_a_ln_w, out);

    // 4) merged up-projections with fused scatter epilogues
    //    q: 6144 = 32 x 192; kv: ceil(8192/192) = 43 tiles (edge guarded)
    gemm_up<<<dim3(75, 64), blk, SMEM>>>(qat, w3, ckvnt, w4, out);
}